// round 15
// baseline (speedup 1.0000x reference)
#include <cuda_runtime.h>
#include <math.h>
#include <stdint.h>

// Problem constants
#define B_   16
#define C_   512
#define NH_  8
#define HD_  64
#define N_   1024
#define QSCALE 0.125f

typedef unsigned long long ull;

// ---------------------------------------------------------------------------
// Scratch (device globals) — pure fp32 pipeline.
// ---------------------------------------------------------------------------
__device__ float g_qkv[(size_t)3 * B_ * C_ * N_];   // [s][b][c][n] (Q pre-scaled)
__device__ float g_attn[(size_t)B_ * C_ * N_];      // [b][c][n]

// ---------------------------------------------------------------------------
// Packed f32x2 helpers (sm_100+ family PTX)
// ---------------------------------------------------------------------------
__device__ __forceinline__ ull pk2(float x, float y) {
    ull r;
    asm("mov.b64 %0, {%1, %2};"
        : "=l"(r) : "r"(__float_as_uint(x)), "r"(__float_as_uint(y)));
    return r;
}
__device__ __forceinline__ void up2(ull v, float& x, float& y) {
    uint32_t a, b;
    asm("mov.b64 {%0, %1}, %2;" : "=r"(a), "=r"(b) : "l"(v));
    x = __uint_as_float(a); y = __uint_as_float(b);
}
__device__ __forceinline__ ull fma2(ull a, ull b, ull c) {
    ull d;
    asm("fma.rn.f32x2 %0, %1, %2, %3;" : "=l"(d) : "l"(a), "l"(b), "l"(c));
    return d;
}
__device__ __forceinline__ ull mul2(ull a, ull b) {
    ull d;
    asm("mul.rn.f32x2 %0, %1, %2;" : "=l"(d) : "l"(a), "l"(b));
    return d;
}
__device__ __forceinline__ uint32_t smem_u32(const void* p) {
    uint32_t a;
    asm("{ .reg .u64 t; cvta.to.shared.u64 t, %1; cvt.u32.u64 %0, t; }" : "=r"(a) : "l"(p));
    return a;
}
// 4-byte async copy global -> shared (Ampere+, non-'a')
__device__ __forceinline__ void cpa4(uint32_t dst, const float* src) {
    asm volatile("cp.async.ca.shared.global [%0], [%1], 4;" :: "r"(dst), "l"(src) : "memory");
}

// ---------------------------------------------------------------------------
// f32x2 GEMM (R9-EXACT — measured 743 us / ~250 us, ~93% of fma2 pipe bound):
// D[o][n] = sum_c W[o][c] * X[b][c][n].
// Block 128(o) x 128(n), BK=16, 256 threads (16x16), 8x8 micro-tile.
// MODE 0: scatter fp32 into g_qkv (Q rows scaled).  MODE 1: +bias -> out.
// ---------------------------------------------------------------------------
template<int MODE>
__global__ __launch_bounds__(256)
void gemm_f32x2(const float* __restrict__ W, const float* __restrict__ Xin,
                const float* __restrict__ bias, float* __restrict__ out)
{
    __shared__ ull   As2[16][128];   // [k][o], each entry = (a, a)   (16 KB)
    __shared__ float Bs[16][128];    // [k][n]                         (8 KB)

    const int b  = blockIdx.z;
    const int o0 = blockIdx.x * 128;
    const int n0 = blockIdx.y * 128;
    const int tid = threadIdx.x;
    const int tx = tid & 15, ty = tid >> 4;

    const float* Xb = (MODE == 1 ? g_attn : Xin) + (size_t)b * C_ * N_;

    ull acc[8][4];
    #pragma unroll
    for (int i = 0; i < 8; i++)
        #pragma unroll
        for (int j = 0; j < 4; j++) acc[i][j] = 0ull;

    for (int kt = 0; kt < C_; kt += 16) {
        #pragma unroll
        for (int r = 0; r < 2; r++) {
            int idx = tid + r * 256;           // 0..511 float4 units
            int m = idx >> 2, q = idx & 3;
            float4 a4 = *(const float4*)&W[(size_t)(o0 + m) * C_ + kt + q * 4];
            As2[q * 4 + 0][m] = pk2(a4.x, a4.x);
            As2[q * 4 + 1][m] = pk2(a4.y, a4.y);
            As2[q * 4 + 2][m] = pk2(a4.z, a4.z);
            As2[q * 4 + 3][m] = pk2(a4.w, a4.w);
        }
        #pragma unroll
        for (int r = 0; r < 2; r++) {
            int idx = tid + r * 256;           // 0..511 float4 units
            int k = idx >> 5, j4 = idx & 31;
            *(float4*)&Bs[k][j4 * 4] =
                *(const float4*)&Xb[(size_t)(kt + k) * N_ + n0 + j4 * 4];
        }
        __syncthreads();

        #pragma unroll
        for (int k = 0; k < 16; k++) {
            ull aa[8];
            #pragma unroll
            for (int i = 0; i < 8; i++) aa[i] = As2[k][ty * 8 + i];
            ulonglong2 b20 = *(const ulonglong2*)&Bs[k][tx * 8];
            ulonglong2 b21 = *(const ulonglong2*)&Bs[k][tx * 8 + 4];
            ull b2[4] = { b20.x, b20.y, b21.x, b21.y };
            #pragma unroll
            for (int i = 0; i < 8; i++)
                #pragma unroll
                for (int j = 0; j < 4; j++)
                    acc[i][j] = fma2(aa[i], b2[j], acc[i][j]);
        }
        __syncthreads();
    }

    #pragma unroll
    for (int i = 0; i < 8; i++) {
        int o = o0 + ty * 8 + i;
        float scale = 1.f, bv = 0.f;
        float* dst;
        if (MODE == 0) {
            int s = o >> 9, rem = o & 511;
            if (s == 0) scale = QSCALE;
            dst = g_qkv + (((size_t)s * B_ + b) * C_ + rem) * N_ + n0;
        } else {
            bv = bias[o];
            dst = out + ((size_t)b * C_ + o) * N_ + n0;
        }
        #pragma unroll
        for (int j = 0; j < 4; j++) {
            float x, y;
            up2(acc[i][j], x, y);
            float2 v;
            if (MODE == 0) { v.x = x * scale; v.y = y * scale; }
            else           { v.x = x + bv;    v.y = y + bv; }
            *(float2*)(dst + tx * 8 + j * 2) = v;
        }
    }
}

// ---------------------------------------------------------------------------
// f32x2 flash attention v4: R9 compute body, cp.async DOUBLE-BUFFERED tiles.
// 1 thread = 1 query; K/V smem layout [j][d] (stride 68, 16B-aligned rows).
// Transposed gmem->smem scatter done via 4B cp.async: no registers held,
// store conflicts off the warp path, next tile's gmem latency overlapped
// with current tile's compute.
// Dynamic smem: 4 buffers x 64x68 floats = 69632 B.
// ---------------------------------------------------------------------------
#define TILEF (64 * 68)
#define ATTN_SMEM (4 * TILEF * 4)

__global__ __launch_bounds__(128, 3)
void attn_f32x2()
{
    extern __shared__ float sm[];   // [K0 | K1 | V0 | V1], each 64x68

    const int bh = blockIdx.x;
    const int b  = bh >> 3, h = bh & 7;
    const int tid = threadIdx.x;
    const int n  = blockIdx.y * 128 + tid;

    const size_t headoff = ((size_t)b * C_ + h * HD_) * N_;
    const float* Qg = g_qkv + headoff;                               // pre-scaled
    const float* Kg = g_qkv + (size_t)1 * B_ * C_ * N_ + headoff;
    const float* Vg = g_qkv + (size_t)2 * B_ * C_ * N_ + headoff;

    const uint32_t smb = smem_u32(sm);
    // per-thread cp.async geometry: j fixed, d = 2*i + (tid>>6)
    const int cj = tid & 63, cth = tid >> 6;

    // issue tile (t0 = key offset) into buffer `buf`
#define ISSUE_TILE(t0, buf) do {                                              \
        const float* _ks = Kg + (size_t)cth * N_ + (t0) + cj;                 \
        const float* _vs = Vg + (size_t)cth * N_ + (t0) + cj;                 \
        uint32_t _kd = smb + (uint32_t)(buf) * (TILEF * 4)                    \
                           + (uint32_t)(cj * 68 + cth) * 4;                   \
        uint32_t _vd = _kd + 2u * (TILEF * 4);                                \
        _Pragma("unroll")                                                     \
        for (int i = 0; i < 32; i++) {                                        \
            cpa4(_kd + (uint32_t)(8 * i), _ks + (size_t)(2 * i) * N_);        \
            cpa4(_vd + (uint32_t)(8 * i), _vs + (size_t)(2 * i) * N_);        \
        }                                                                     \
    } while (0)

    ull q2[32], o2[32];
    #pragma unroll
    for (int dp = 0; dp < 32; dp++) {
        q2[dp] = pk2(Qg[(size_t)(2 * dp) * N_ + n], Qg[(size_t)(2 * dp + 1) * N_ + n]);
        o2[dp] = 0ull;
    }
    float m = -INFINITY, l = 0.f;

    // prologue: tile 0 -> buffer 0
    ISSUE_TILE(0, 0);
    asm volatile("cp.async.commit_group;" ::: "memory");

    for (int t = 0; t < 16; t++) {
        const int cur = t & 1;
        if (t < 15) {
            ISSUE_TILE((t + 1) * 64, 1 - cur);
            asm volatile("cp.async.commit_group;" ::: "memory");
            asm volatile("cp.async.wait_group 1;" ::: "memory");
        } else {
            asm volatile("cp.async.wait_group 0;" ::: "memory");
        }
        __syncthreads();   // tile t visible to all warps

        const float* Kbuf = sm + cur * TILEF;
        const float* Vbuf = sm + (2 + cur) * TILEF;

        for (int j4 = 0; j4 < 16; j4++) {
            // scores for 4 keys (R9-exact)
            float s[4];
            #pragma unroll
            for (int jj = 0; jj < 4; jj++) {
                const ulonglong2* kp = (const ulonglong2*)(Kbuf + (j4 * 4 + jj) * 68);
                ull sa = 0ull, sb = 0ull;
                #pragma unroll
                for (int dq = 0; dq < 16; dq++) {
                    ulonglong2 k2 = kp[dq];         // broadcast LDS.128
                    sa = fma2(q2[2 * dq],     k2.x, sa);
                    sb = fma2(q2[2 * dq + 1], k2.y, sb);
                }
                float ax, ay, bx, by;
                up2(sa, ax, ay); up2(sb, bx, by);
                s[jj] = (ax + bx) + (ay + by);
            }

            // online softmax (lazy rescale)
            float gm = fmaxf(fmaxf(s[0], s[1]), fmaxf(s[2], s[3]));
            if (gm > m) {
                float corr = __expf(m - gm);        // exp(-inf)=0 first tile
                l *= corr;
                ull cc = pk2(corr, corr);
                #pragma unroll
                for (int dp = 0; dp < 32; dp++) o2[dp] = mul2(o2[dp], cc);
                m = gm;
            }
            float p[4];
            #pragma unroll
            for (int jj = 0; jj < 4; jj++) { p[jj] = __expf(s[jj] - m); l += p[jj]; }

            // PV accumulate (R9-exact)
            #pragma unroll
            for (int jj = 0; jj < 4; jj++) {
                ull pp = pk2(p[jj], p[jj]);
                const ulonglong2* vp = (const ulonglong2*)(Vbuf + (j4 * 4 + jj) * 68);
                #pragma unroll
                for (int dq = 0; dq < 16; dq++) {
                    ulonglong2 v2 = vp[dq];         // broadcast LDS.128
                    o2[2 * dq]     = fma2(pp, v2.x, o2[2 * dq]);
                    o2[2 * dq + 1] = fma2(pp, v2.y, o2[2 * dq + 1]);
                }
            }
        }
        __syncthreads();   // all reads of buf[cur] done before it is re-issued
    }

    const float inv = 1.f / l;
    float* Og = g_attn + headoff;
    #pragma unroll
    for (int dp = 0; dp < 32; dp++) {
        float x, y;
        up2(o2[dp], x, y);
        Og[(size_t)(2 * dp) * N_ + n]     = x * inv;   // coalesced per d
        Og[(size_t)(2 * dp + 1) * N_ + n] = y * inv;
    }
#undef ISSUE_TILE
}

// ---------------------------------------------------------------------------
extern "C" void kernel_launch(void* const* d_in, const int* in_sizes, int n_in,
                              void* d_out, int out_size)
{
    const float* x      = (const float*)d_in[0];   // [B, C, H, W]
    const float* w_qkv  = (const float*)d_in[1];   // [3C, C]
    const float* w_proj = (const float*)d_in[2];   // [C, C]
    const float* b_proj = (const float*)d_in[3];   // [C]
    float* out = (float*)d_out;

    // attn needs >48KB dynamic smem (idempotent attribute set, not a stream op)
    cudaFuncSetAttribute(attn_f32x2, cudaFuncAttributeMaxDynamicSharedMemorySize,
                         ATTN_SMEM);

    // 1) QKV GEMM (f32x2, R9-exact) -> g_qkv, Q scaled
    gemm_f32x2<0><<<dim3(3 * C_ / 128, N_ / 128, B_), 256>>>(w_qkv, x, nullptr, nullptr);

    // 2) flash attention (f32x2, cp.async double-buffered) -> g_attn
    attn_f32x2<<<dim3(B_ * NH_, N_ / 128), 128, ATTN_SMEM>>>();

    // 3) proj GEMM (f32x2, R9-exact) + bias -> out
    gemm_f32x2<1><<<dim3(C_ / 128, N_ / 128, B_), 256>>>(w_proj, nullptr, b_proj, out);
}